// round 11
// baseline (speedup 1.0000x reference)
#include <cuda_runtime.h>

#define SEQ_LEN   8192
#define HIDDEN    1024
#define H2        512                 // packed f32x2 per row
#define H4        256                 // float4 per row
#define NUM_SPANS 4096
#define MAX_W     32
#define SPB       8                   // sorted spans per block
#define WCAP      64                  // max union-window rows for fast path
#define SCORE_BLOCKS 256              // 1024-thr blocks: 32 rows each

__device__ float g_scores[SEQ_LEN];
__device__ int   g_sorted[NUM_SPANS];

typedef unsigned long long ull;

// packed f32x2 fma: d = a*b + d
__device__ __forceinline__ void ffma2(ull& d, ull a, ull b) {
    asm("fma.rn.f32x2 %0, %1, %2, %0;" : "+l"(d) : "l"(a), "l"(b));
}
__device__ __forceinline__ ull packf2(float lo, float hi) {
    ull r; asm("mov.b64 %0, {%1, %2};" : "=l"(r) : "f"(lo), "f"(hi)); return r;
}

// ---------------- Kernel 1: scores (blocks 0..255) + full sort (block 256) -
__global__ __launch_bounds__(1024) void setup_kernel(
        const float* __restrict__ emb,
        const float* __restrict__ attn_w,
        const float* __restrict__ attn_b,
        const int*   __restrict__ starts) {
    __shared__ int s_cnt[SEQ_LEN];        // 32 KB: sort histogram/offsets
    __shared__ int s_wtot[32];

    if (blockIdx.x < SCORE_BLOCKS) {
        // ---- per-position logits: one warp per row, 32 rows/block ----
        int warp = (blockIdx.x * 1024 + threadIdx.x) >> 5;
        int lane = threadIdx.x & 31;

        const float4* row = (const float4*)(emb) + (size_t)warp * H4;
        const float4* wv  = (const float4*)(attn_w);

        float acc = 0.0f;
#pragma unroll
        for (int j = 0; j < H4 / 32; j++) {
            float4 a = row[j * 32 + lane];
            float4 c = wv [j * 32 + lane];
            acc += a.x * c.x + a.y * c.y + a.z * c.z + a.w * c.w;
        }
#pragma unroll
        for (int off = 16; off; off >>= 1)
            acc += __shfl_xor_sync(0xffffffffu, acc, off);

        if (lane == 0) g_scores[warp] = acc + attn_b[0];
        return;
    }

    // ---- block 256: counting sort of spans by start, entirely in smem ----
    const int t = threadIdx.x;            // 1024 threads
    for (int i = t; i < SEQ_LEN; i += 1024) s_cnt[i] = 0;
    __syncthreads();

    for (int j = t; j < NUM_SPANS; j += 1024)
        atomicAdd(&s_cnt[starts[j]], 1);
    __syncthreads();

    // exclusive scan of 8192 counters: 8 per thread
    const int base = t * 8;
    int loc[8];
    int tsum = 0;
#pragma unroll
    for (int i = 0; i < 8; i++) { loc[i] = tsum; tsum += s_cnt[base + i]; }

    const int lane = t & 31, wid = t >> 5;
    int x = tsum;
#pragma unroll
    for (int off = 1; off < 32; off <<= 1) {
        int y = __shfl_up_sync(0xffffffffu, x, off);
        if (lane >= off) x += y;
    }
    if (lane == 31) s_wtot[wid] = x;
    __syncthreads();
    if (wid == 0) {
        int s = s_wtot[lane];
#pragma unroll
        for (int off = 1; off < 32; off <<= 1) {
            int y = __shfl_up_sync(0xffffffffu, s, off);
            if (lane >= off) s += y;
        }
        s_wtot[lane] = s;
    }
    __syncthreads();

    int excl = x - tsum + (wid ? s_wtot[wid - 1] : 0);
#pragma unroll
    for (int i = 0; i < 8; i++) s_cnt[base + i] = excl + loc[i];
    __syncthreads();

    for (int j = t; j < NUM_SPANS; j += 1024) {
        int p = atomicAdd(&s_cnt[starts[j]], 1);
        g_sorted[p] = j;
    }
}

// ---------------- Kernel 2: main — 512 thr, 1 f32x2 column per thread -----
__global__ __launch_bounds__(512, 2) void span_main(
        const float* __restrict__ emb,
        const int*   __restrict__ starts,
        const int*   __restrict__ ends,
        float*       __restrict__ out) {
    __shared__ ulonglong2 s_wt[WCAP][SPB / 2];        // zero-padded, 4 KB
    __shared__ ull s_wp[SPB][MAX_W];                  // per-span packed weights
    __shared__ int s_s[SPB], s_wd[SPB], s_j[SPB];

    const int tid  = threadIdx.x;         // 512 == H2: one f32x2 column/thread
    const int wid  = tid >> 5;            // 0..15
    const int lane = tid & 31;

    if (wid < SPB) {
        // ---- warp w: softmax for slot w ----
        int j = g_sorted[blockIdx.x * SPB + wid];
        int s = starts[j];
        int W = ends[j] - s;              // width-1 in [0,31]
        float sc = (lane <= W) ? g_scores[s + lane] : -1e9f;
        float m = sc;
#pragma unroll
        for (int off = 16; off; off >>= 1)
            m = fmaxf(m, __shfl_xor_sync(0xffffffffu, m, off));
        float p = __expf(sc - m);
        float sum = p;
#pragma unroll
        for (int off = 16; off; off >>= 1)
            sum += __shfl_xor_sync(0xffffffffu, sum, off);
        float wgt = p / sum;
        s_wp[wid][lane] = packf2(wgt, wgt);
        if (lane == 0) { s_s[wid] = s; s_wd[wid] = W; s_j[wid] = j; }
    } else {
        // ---- warps 8-15: zero the weight table (256 ulonglong2 entries) ----
        ((ulonglong2*)s_wt)[tid - 256] = make_ulonglong2(0ull, 0ull);
    }
    __syncthreads();

    const int rmin = s_s[0];              // sorted by start
    int rmax = s_s[0] + s_wd[0];
#pragma unroll
    for (int k = 1; k < SPB; k++) rmax = max(rmax, s_s[k] + s_wd[k]);
    const int win = rmax - rmin + 1;

    const ull* eb = (const ull*)(emb);
    ull*       ob = (ull*)(out);

    if (win <= WCAP) {
        // ---- scatter warp w's weights into the zero-padded table ----
        if (wid < SPB && lane <= s_wd[wid])
            ((ull*)s_wt)[(s_s[wid] - rmin + lane) * SPB + wid] = s_wp[wid][lane];
        __syncthreads();

        ull acc[SPB];
#pragma unroll
        for (int k = 0; k < SPB; k++) acc[k] = 0ull;

        const ull* p = eb + (size_t)rmin * H2 + tid;

        // prefetch row 0; depth-1 pipeline (rmax+1 <= 8191, always in bounds)
        ull v = *p;
        p += H2;

        for (int rw = 0; rw < win; rw++) {
            ull vn = *p;                   // next row, consumed next iter
            p += H2;
            ulonglong2 w01 = s_wt[rw][0];
            ulonglong2 w23 = s_wt[rw][1];
            ulonglong2 w45 = s_wt[rw][2];
            ulonglong2 w67 = s_wt[rw][3];
            ffma2(acc[0], w01.x, v);
            ffma2(acc[1], w01.y, v);
            ffma2(acc[2], w23.x, v);
            ffma2(acc[3], w23.y, v);
            ffma2(acc[4], w45.x, v);
            ffma2(acc[5], w45.y, v);
            ffma2(acc[6], w67.x, v);
            ffma2(acc[7], w67.y, v);
            v = vn;
        }

        // ---- epilogue: attn_out + start/end copies (window rows are hot) ----
#pragma unroll
        for (int k = 0; k < SPB; k++) {
            int obase = s_j[k] * (3 * H2);
            int s0 = s_s[k];
            ob[obase + 2 * H2 + tid] = acc[k];
            ull sv = eb[(size_t)s0 * H2 + tid];
            ull ev = eb[(size_t)(s0 + s_wd[k]) * H2 + tid];
            ob[obase + tid]      = sv;
            ob[obase + H2 + tid] = ev;
        }
    } else {
        // ---- rare slow path: all threads sweep each span in turn ----
        for (int k = 0; k < SPB; k++) {
            int s0 = s_s[k], W = s_wd[k];
            int obase = s_j[k] * (3 * H2);
            const ull* bp = eb + (size_t)s0 * H2 + tid;
            ull acc = 0ull;
            for (int r = 0; r <= W; r++) {
                ull w2 = s_wp[k][r];       // broadcast LDS
                ffma2(acc, w2, bp[(size_t)r * H2]);
            }
            ob[obase + 2 * H2 + tid] = acc;
            ob[obase + tid]          = bp[0];
            ob[obase + H2 + tid]     = bp[(size_t)W * H2];
        }
    }
}

extern "C" void kernel_launch(void* const* d_in, const int* in_sizes, int n_in,
                              void* d_out, int out_size) {
    const float* emb    = (const float*)d_in[0];
    const int*   starts = (const int*)  d_in[1];
    const int*   ends   = (const int*)  d_in[2];
    const float* attn_w = (const float*)d_in[3];
    const float* attn_b = (const float*)d_in[4];
    float*       out    = (float*)d_out;

    setup_kernel<<<SCORE_BLOCKS + 1, 1024>>>(emb, attn_w, attn_b, starts);
    span_main<<<NUM_SPANS / SPB, 512>>>(emb, starts, ends, out);
}

// round 14
// speedup vs baseline: 1.0101x; 1.0101x over previous
#include <cuda_runtime.h>

#define SEQ_LEN   8192
#define HIDDEN    1024
#define H2        512                 // packed f32x2 per row
#define H4        256                 // float4 per row
#define NUM_SPANS 4096
#define MAX_W     32
#define SPB       8                   // sorted spans per block
#define WCAP      64                  // max union-window rows for fast path
#define SCORE_BLOCKS 256              // 1024-thr blocks: 32 rows each

__device__ float g_scores[SEQ_LEN];
__device__ int   g_sorted[NUM_SPANS];

typedef unsigned long long ull;

// packed f32x2 fma: d = a*b + d
__device__ __forceinline__ void ffma2(ull& d, ull a, ull b) {
    asm("fma.rn.f32x2 %0, %1, %2, %0;" : "+l"(d) : "l"(a), "l"(b));
}
__device__ __forceinline__ ull packf2(float lo, float hi) {
    ull r; asm("mov.b64 %0, {%1, %2};" : "=l"(r) : "f"(lo), "f"(hi)); return r;
}

// ---------------- Kernel 1: scores (blocks 0..255) + full sort (block 256) -
__global__ __launch_bounds__(1024) void setup_kernel(
        const float* __restrict__ emb,
        const float* __restrict__ attn_w,
        const float* __restrict__ attn_b,
        const int*   __restrict__ starts) {
    __shared__ int s_cnt[SEQ_LEN];        // 32 KB: sort histogram/offsets
    __shared__ int s_wtot[32];

    if (blockIdx.x < SCORE_BLOCKS) {
        // ---- per-position logits: one warp per row, 32 rows/block ----
        int warp = (blockIdx.x * 1024 + threadIdx.x) >> 5;
        int lane = threadIdx.x & 31;

        const float4* row = (const float4*)(emb) + (size_t)warp * H4;
        const float4* wv  = (const float4*)(attn_w);

        float acc = 0.0f;
#pragma unroll
        for (int j = 0; j < H4 / 32; j++) {
            float4 a = row[j * 32 + lane];
            float4 c = wv [j * 32 + lane];
            acc += a.x * c.x + a.y * c.y + a.z * c.z + a.w * c.w;
        }
#pragma unroll
        for (int off = 16; off; off >>= 1)
            acc += __shfl_xor_sync(0xffffffffu, acc, off);

        if (lane == 0) g_scores[warp] = acc + attn_b[0];
        return;
    }

    // ---- block 256: counting sort of spans by start, entirely in smem ----
    const int t = threadIdx.x;            // 1024 threads
    for (int i = t; i < SEQ_LEN; i += 1024) s_cnt[i] = 0;
    __syncthreads();

    for (int j = t; j < NUM_SPANS; j += 1024)
        atomicAdd(&s_cnt[starts[j]], 1);
    __syncthreads();

    // exclusive scan of 8192 counters: 8 per thread
    const int base = t * 8;
    int loc[8];
    int tsum = 0;
#pragma unroll
    for (int i = 0; i < 8; i++) { loc[i] = tsum; tsum += s_cnt[base + i]; }

    const int lane = t & 31, wid = t >> 5;
    int x = tsum;
#pragma unroll
    for (int off = 1; off < 32; off <<= 1) {
        int y = __shfl_up_sync(0xffffffffu, x, off);
        if (lane >= off) x += y;
    }
    if (lane == 31) s_wtot[wid] = x;
    __syncthreads();
    if (wid == 0) {
        int s = s_wtot[lane];
#pragma unroll
        for (int off = 1; off < 32; off <<= 1) {
            int y = __shfl_up_sync(0xffffffffu, s, off);
            if (lane >= off) s += y;
        }
        s_wtot[lane] = s;
    }
    __syncthreads();

    int excl = x - tsum + (wid ? s_wtot[wid - 1] : 0);
#pragma unroll
    for (int i = 0; i < 8; i++) s_cnt[base + i] = excl + loc[i];
    __syncthreads();

    for (int j = t; j < NUM_SPANS; j += 1024) {
        int p = atomicAdd(&s_cnt[starts[j]], 1);
        g_sorted[p] = j;
    }
}

// ---------------- Kernel 2: main — 512 thr, unroll-2 + pair prefetch ------
__global__ __launch_bounds__(512, 2) void span_main(
        const float* __restrict__ emb,
        const int*   __restrict__ starts,
        const int*   __restrict__ ends,
        float*       __restrict__ out) {
    __shared__ ulonglong2 s_wt[WCAP][SPB / 2];        // zero-padded, 4 KB
    __shared__ ull s_wp[SPB][MAX_W];                  // per-span packed weights
    __shared__ int s_s[SPB], s_wd[SPB], s_j[SPB];

    const int tid  = threadIdx.x;         // 512 == H2: one f32x2 column/thread
    const int wid  = tid >> 5;            // 0..15
    const int lane = tid & 31;

    if (wid < SPB) {
        // ---- warp w: softmax for slot w ----
        int j = g_sorted[blockIdx.x * SPB + wid];
        int s = starts[j];
        int W = ends[j] - s;              // width-1 in [0,31]
        float sc = (lane <= W) ? g_scores[s + lane] : -1e9f;
        float m = sc;
#pragma unroll
        for (int off = 16; off; off >>= 1)
            m = fmaxf(m, __shfl_xor_sync(0xffffffffu, m, off));
        float p = __expf(sc - m);
        float sum = p;
#pragma unroll
        for (int off = 16; off; off >>= 1)
            sum += __shfl_xor_sync(0xffffffffu, sum, off);
        float wgt = p / sum;
        s_wp[wid][lane] = packf2(wgt, wgt);
        if (lane == 0) { s_s[wid] = s; s_wd[wid] = W; s_j[wid] = j; }
    } else {
        // ---- warps 8-15: zero the weight table (256 ulonglong2 entries) ----
        ((ulonglong2*)s_wt)[tid - 256] = make_ulonglong2(0ull, 0ull);
    }
    __syncthreads();

    const int rmin = s_s[0];              // sorted by start
    int rmax = s_s[0] + s_wd[0];
#pragma unroll
    for (int k = 1; k < SPB; k++) rmax = max(rmax, s_s[k] + s_wd[k]);
    const int win = rmax - rmin + 1;

    const ull* eb = (const ull*)(emb);
    ull*       ob = (ull*)(out);

    if (win <= WCAP) {
        // ---- scatter warp w's weights into the zero-padded table ----
        if (wid < SPB && lane <= s_wd[wid])
            ((ull*)s_wt)[(s_s[wid] - rmin + lane) * SPB + wid] = s_wp[wid][lane];
        __syncthreads();

        ull acc[SPB];
#pragma unroll
        for (int k = 0; k < SPB; k++) acc[k] = 0ull;

        const ull* colp = eb + tid;

        // pair prefetch, clamped (rows past the window have zero weights,
        // clamped rows are multiplied by zero -> exact no-ops)
        ull v0 = colp[(size_t)rmin * H2];
        ull v1 = colp[(size_t)min(rmin + 1, SEQ_LEN - 1) * H2];

        for (int rw = 0; rw < win; rw += 2) {
            int rn  = min(rmin + rw + 2, SEQ_LEN - 1);
            int rn1 = min(rmin + rw + 3, SEQ_LEN - 1);
            ull vn0 = colp[(size_t)rn  * H2];
            ull vn1 = colp[(size_t)rn1 * H2];

            {   // row rw
                ulonglong2 w01 = s_wt[rw][0];
                ulonglong2 w23 = s_wt[rw][1];
                ulonglong2 w45 = s_wt[rw][2];
                ulonglong2 w67 = s_wt[rw][3];
                ffma2(acc[0], w01.x, v0);
                ffma2(acc[1], w01.y, v0);
                ffma2(acc[2], w23.x, v0);
                ffma2(acc[3], w23.y, v0);
                ffma2(acc[4], w45.x, v0);
                ffma2(acc[5], w45.y, v0);
                ffma2(acc[6], w67.x, v0);
                ffma2(acc[7], w67.y, v0);
            }
            {   // row rw+1 (zero-padded if beyond win)
                ulonglong2 w01 = s_wt[rw + 1][0];
                ulonglong2 w23 = s_wt[rw + 1][1];
                ulonglong2 w45 = s_wt[rw + 1][2];
                ulonglong2 w67 = s_wt[rw + 1][3];
                ffma2(acc[0], w01.x, v1);
                ffma2(acc[1], w01.y, v1);
                ffma2(acc[2], w23.x, v1);
                ffma2(acc[3], w23.y, v1);
                ffma2(acc[4], w45.x, v1);
                ffma2(acc[5], w45.y, v1);
                ffma2(acc[6], w67.x, v1);
                ffma2(acc[7], w67.y, v1);
            }
            v0 = vn0;
            v1 = vn1;
        }

        // ---- epilogue: attn_out + start/end copies (window rows are hot) ----
#pragma unroll
        for (int k = 0; k < SPB; k++) {
            int obase = s_j[k] * (3 * H2);
            int s0 = s_s[k];
            ob[obase + 2 * H2 + tid] = acc[k];
            ull sv = eb[(size_t)s0 * H2 + tid];
            ull ev = eb[(size_t)(s0 + s_wd[k]) * H2 + tid];
            ob[obase + tid]      = sv;
            ob[obase + H2 + tid] = ev;
        }
    } else {
        // ---- rare slow path: all threads sweep each span in turn ----
        for (int k = 0; k < SPB; k++) {
            int s0 = s_s[k], W = s_wd[k];
            int obase = s_j[k] * (3 * H2);
            const ull* bp = eb + (size_t)s0 * H2 + tid;
            ull acc = 0ull;
            for (int r = 0; r <= W; r++) {
                ull w2 = s_wp[k][r];       // broadcast LDS
                ffma2(acc, w2, bp[(size_t)r * H2]);
            }
            ob[obase + 2 * H2 + tid] = acc;
            ob[obase + tid]          = bp[0];
            ob[obase + H2 + tid]     = bp[(size_t)W * H2];
        }
    }
}

extern "C" void kernel_launch(void* const* d_in, const int* in_sizes, int n_in,
                              void* d_out, int out_size) {
    const float* emb    = (const float*)d_in[0];
    const int*   starts = (const int*)  d_in[1];
    const int*   ends   = (const int*)  d_in[2];
    const float* attn_w = (const float*)d_in[3];
    const float* attn_b = (const float*)d_in[4];
    float*       out    = (float*)d_out;

    setup_kernel<<<SCORE_BLOCKS + 1, 1024>>>(emb, attn_w, attn_b, starts);
    span_main<<<NUM_SPANS / SPB, 512>>>(emb, starts, ends, out);
}

// round 15
// speedup vs baseline: 1.0128x; 1.0028x over previous
#include <cuda_runtime.h>

#define SEQ_LEN   8192
#define HIDDEN    1024
#define H2        512                 // f32x2 (ull) per full row
#define HH        256                 // ull per half row
#define H4        256                 // float4 per row
#define NUM_SPANS 4096
#define MAX_W     32
#define SPB       8                   // sorted spans per group
#define WCAP      64                  // max union-window rows (zero-padded)
#define NB        4                   // rows per prefetch batch
#define SCORE_BLOCKS 256              // 1024-thr blocks: 32 rows each

__device__ float g_scores[SEQ_LEN];
__device__ int   g_sorted[NUM_SPANS];

typedef unsigned long long ull;

__device__ __forceinline__ void ffma2(ull& d, ull a, ull b) {
    asm("fma.rn.f32x2 %0, %1, %2, %0;" : "+l"(d) : "l"(a), "l"(b));
}
__device__ __forceinline__ ull packf2(float lo, float hi) {
    ull r; asm("mov.b64 %0, {%1, %2};" : "=l"(r) : "f"(lo), "f"(hi)); return r;
}

// ---------------- Kernel 1: scores (blocks 0..255) + full sort (block 256) -
__global__ __launch_bounds__(1024) void setup_kernel(
        const float* __restrict__ emb,
        const float* __restrict__ attn_w,
        const float* __restrict__ attn_b,
        const int*   __restrict__ starts) {
    __shared__ int s_cnt[SEQ_LEN];        // 32 KB
    __shared__ int s_wtot[32];

    if (blockIdx.x < SCORE_BLOCKS) {
        int warp = (blockIdx.x * 1024 + threadIdx.x) >> 5;
        int lane = threadIdx.x & 31;

        const float4* row = (const float4*)(emb) + (size_t)warp * H4;
        const float4* wv  = (const float4*)(attn_w);

        float acc = 0.0f;
#pragma unroll
        for (int j = 0; j < H4 / 32; j++) {
            float4 a = row[j * 32 + lane];
            float4 c = wv [j * 32 + lane];
            acc += a.x * c.x + a.y * c.y + a.z * c.z + a.w * c.w;
        }
#pragma unroll
        for (int off = 16; off; off >>= 1)
            acc += __shfl_xor_sync(0xffffffffu, acc, off);

        if (lane == 0) g_scores[warp] = acc + attn_b[0];
        return;
    }

    const int t = threadIdx.x;            // 1024 threads
    for (int i = t; i < SEQ_LEN; i += 1024) s_cnt[i] = 0;
    __syncthreads();

    for (int j = t; j < NUM_SPANS; j += 1024)
        atomicAdd(&s_cnt[starts[j]], 1);
    __syncthreads();

    const int base = t * 8;
    int loc[8];
    int tsum = 0;
#pragma unroll
    for (int i = 0; i < 8; i++) { loc[i] = tsum; tsum += s_cnt[base + i]; }

    const int lane = t & 31, wid = t >> 5;
    int x = tsum;
#pragma unroll
    for (int off = 1; off < 32; off <<= 1) {
        int y = __shfl_up_sync(0xffffffffu, x, off);
        if (lane >= off) x += y;
    }
    if (lane == 31) s_wtot[wid] = x;
    __syncthreads();
    if (wid == 0) {
        int s = s_wtot[lane];
#pragma unroll
        for (int off = 1; off < 32; off <<= 1) {
            int y = __shfl_up_sync(0xffffffffu, s, off);
            if (lane >= off) s += y;
        }
        s_wtot[lane] = s;
    }
    __syncthreads();

    int excl = x - tsum + (wid ? s_wtot[wid - 1] : 0);
#pragma unroll
    for (int i = 0; i < 8; i++) s_cnt[base + i] = excl + loc[i];
    __syncthreads();

    for (int j = t; j < NUM_SPANS; j += 1024) {
        int p = atomicAdd(&s_cnt[starts[j]], 1);
        g_sorted[p] = j;
    }
}

// ---- Kernel 2: 256 thr, half-hidden per block, 4-row batched prefetch ----
__global__ __launch_bounds__(256) void span_main(
        const float* __restrict__ emb,
        const int*   __restrict__ starts,
        const int*   __restrict__ ends,
        float*       __restrict__ out) {
    __shared__ ull s_wt[WCAP][SPB];       // zero-padded weight table, 4 KB
    __shared__ ull s_wp[SPB][MAX_W];      // per-span weights (slow path)
    __shared__ int s_s[SPB], s_wd[SPB], s_j[SPB];

    const int tid  = threadIdx.x;         // one f32x2 column of the half-row
    const int wid  = tid >> 5;
    const int lane = tid & 31;
    const int grp  = blockIdx.x >> 1;     // span group (8 sorted spans)
    const int h    = blockIdx.x & 1;      // hidden half

    if (wid < SPB) {
        // ---- warp w: softmax for slot w ----
        int j = g_sorted[grp * SPB + wid];
        int s = starts[j];
        int W = ends[j] - s;              // width-1 in [0,31]
        float sc = (lane <= W) ? g_scores[s + lane] : -1e9f;
        float m = sc;
#pragma unroll
        for (int off = 16; off; off >>= 1)
            m = fmaxf(m, __shfl_xor_sync(0xffffffffu, m, off));
        float p = __expf(sc - m);
        float sum = p;
#pragma unroll
        for (int off = 16; off; off >>= 1)
            sum += __shfl_xor_sync(0xffffffffu, sum, off);
        float wgt = p / sum;
        s_wp[wid][lane] = packf2(wgt, wgt);
        if (lane == 0) { s_s[wid] = s; s_wd[wid] = W; s_j[wid] = j; }
    }
    // zero the table: 512 ull / 256 threads
    ((ull*)s_wt)[tid]       = 0ull;
    ((ull*)s_wt)[tid + 256] = 0ull;
    __syncthreads();

    const int rmin = s_s[0];              // sorted by start
    int rmax = s_s[0] + s_wd[0];
#pragma unroll
    for (int k = 1; k < SPB; k++) rmax = max(rmax, s_s[k] + s_wd[k]);
    const int win = rmax - rmin + 1;

    const ull* colp = (const ull*)(emb) + h * HH + tid;   // + r*H2 per row
    ull*       ob   = (ull*)(out);

    if (win <= WCAP) {
        // scatter weights into the zero-padded table
        if (wid < SPB && lane <= s_wd[wid])
            s_wt[s_s[wid] - rmin + lane][wid] = s_wp[wid][lane];
        __syncthreads();

        ull acc[SPB];
#pragma unroll
        for (int k = 0; k < SPB; k++) acc[k] = 0ull;

        const int nb = (win + NB - 1) / NB;

        // prefetch batch 0 (clamped; out-of-window rows have zero weights)
        ull v[NB];
#pragma unroll
        for (int i = 0; i < NB; i++)
            v[i] = colp[(size_t)min(rmin + i, SEQ_LEN - 1) * H2];

        for (int b = 0; b < nb; b++) {
            ull vn[NB];
            int rb = rmin + (b + 1) * NB;
#pragma unroll
            for (int i = 0; i < NB; i++)
                vn[i] = colp[(size_t)min(rb + i, SEQ_LEN - 1) * H2];

            const int rw0 = b * NB;
#pragma unroll
            for (int i = 0; i < NB; i++) {
                const ulonglong2* wrow = (const ulonglong2*)s_wt[rw0 + i];
                ulonglong2 w01 = wrow[0];
                ulonglong2 w23 = wrow[1];
                ulonglong2 w45 = wrow[2];
                ulonglong2 w67 = wrow[3];
                ffma2(acc[0], w01.x, v[i]);
                ffma2(acc[1], w01.y, v[i]);
                ffma2(acc[2], w23.x, v[i]);
                ffma2(acc[3], w23.y, v[i]);
                ffma2(acc[4], w45.x, v[i]);
                ffma2(acc[5], w45.y, v[i]);
                ffma2(acc[6], w67.x, v[i]);
                ffma2(acc[7], w67.y, v[i]);
            }
#pragma unroll
            for (int i = 0; i < NB; i++) v[i] = vn[i];
        }

        // ---- epilogue: attn_out + start/end copies ----
#pragma unroll
        for (int k = 0; k < SPB; k++) {
            int obase = s_j[k] * (3 * H2) + h * HH + tid;
            int s0 = s_s[k];
            ob[obase + 2 * H2] = acc[k];
            ob[obase]          = colp[(size_t)s0 * H2];
            ob[obase + H2]     = colp[(size_t)(s0 + s_wd[k]) * H2];
        }
    } else {
        // ---- rare slow path: sweep each span in turn ----
        for (int k = 0; k < SPB; k++) {
            int s0 = s_s[k], W = s_wd[k];
            int obase = s_j[k] * (3 * H2) + h * HH + tid;
            const ull* bp = colp + (size_t)s0 * H2;
            ull acc = 0ull;
            for (int r = 0; r <= W; r++) {
                ull w2 = s_wp[k][r];       // broadcast LDS
                ffma2(acc, w2, bp[(size_t)r * H2]);
            }
            ob[obase + 2 * H2] = acc;
            ob[obase]          = bp[0];
            ob[obase + H2]     = bp[(size_t)W * H2];
        }
    }
}

extern "C" void kernel_launch(void* const* d_in, const int* in_sizes, int n_in,
                              void* d_out, int out_size) {
    const float* emb    = (const float*)d_in[0];
    const int*   starts = (const int*)  d_in[1];
    const int*   ends   = (const int*)  d_in[2];
    const float* attn_w = (const float*)d_in[3];
    const float* attn_b = (const float*)d_in[4];
    float*       out    = (float*)d_out;

    setup_kernel<<<SCORE_BLOCKS + 1, 1024>>>(emb, attn_w, attn_b, starts);
    span_main<<<(NUM_SPANS / SPB) * 2, 256>>>(emb, starts, ends, out);
}

// round 16
// speedup vs baseline: 1.0534x; 1.0401x over previous
#include <cuda_runtime.h>

#define SEQ_LEN   8192
#define HIDDEN    1024
#define H2        512                 // f32x2 (ull) per full row
#define HH        256                 // ull per half row
#define H4        256                 // float4 per row
#define NUM_SPANS 4096
#define MAX_W     32
#define SPB       8                   // sorted spans per group
#define WCAP      64                  // max union-window rows (fast path)
#define WPAD      (WCAP + 8)          // zero-padded table rows (lookahead safe)
#define SCORE_BLOCKS 256              // 1024-thr blocks: 32 rows each

__device__ float g_scores[SEQ_LEN];
__device__ int   g_sorted[NUM_SPANS];

typedef unsigned long long ull;

__device__ __forceinline__ void ffma2(ull& d, ull a, ull b) {
    asm("fma.rn.f32x2 %0, %1, %2, %0;" : "+l"(d) : "l"(a), "l"(b));
}
__device__ __forceinline__ ull packf2(float lo, float hi) {
    ull r; asm("mov.b64 %0, {%1, %2};" : "=l"(r) : "f"(lo), "f"(hi)); return r;
}

// ---------------- Kernel 1: scores (blocks 0..255) + full sort (block 256) -
__global__ __launch_bounds__(1024) void setup_kernel(
        const float* __restrict__ emb,
        const float* __restrict__ attn_w,
        const float* __restrict__ attn_b,
        const int*   __restrict__ starts) {
    __shared__ int s_cnt[SEQ_LEN];        // 32 KB
    __shared__ int s_wtot[32];

    if (blockIdx.x < SCORE_BLOCKS) {
        int warp = (blockIdx.x * 1024 + threadIdx.x) >> 5;
        int lane = threadIdx.x & 31;

        const float4* row = (const float4*)(emb) + (size_t)warp * H4;
        const float4* wv  = (const float4*)(attn_w);

        float acc = 0.0f;
#pragma unroll
        for (int j = 0; j < H4 / 32; j++) {
            float4 a = row[j * 32 + lane];
            float4 c = wv [j * 32 + lane];
            acc += a.x * c.x + a.y * c.y + a.z * c.z + a.w * c.w;
        }
#pragma unroll
        for (int off = 16; off; off >>= 1)
            acc += __shfl_xor_sync(0xffffffffu, acc, off);

        if (lane == 0) g_scores[warp] = acc + attn_b[0];
        return;
    }

    const int t = threadIdx.x;            // 1024 threads
    for (int i = t; i < SEQ_LEN; i += 1024) s_cnt[i] = 0;
    __syncthreads();

    for (int j = t; j < NUM_SPANS; j += 1024)
        atomicAdd(&s_cnt[starts[j]], 1);
    __syncthreads();

    const int base = t * 8;
    int loc[8];
    int tsum = 0;
#pragma unroll
    for (int i = 0; i < 8; i++) { loc[i] = tsum; tsum += s_cnt[base + i]; }

    const int lane = t & 31, wid = t >> 5;
    int x = tsum;
#pragma unroll
    for (int off = 1; off < 32; off <<= 1) {
        int y = __shfl_up_sync(0xffffffffu, x, off);
        if (lane >= off) x += y;
    }
    if (lane == 31) s_wtot[wid] = x;
    __syncthreads();
    if (wid == 0) {
        int s = s_wtot[lane];
#pragma unroll
        for (int off = 1; off < 32; off <<= 1) {
            int y = __shfl_up_sync(0xffffffffu, s, off);
            if (lane >= off) s += y;
        }
        s_wtot[lane] = s;
    }
    __syncthreads();

    int excl = x - tsum + (wid ? s_wtot[wid - 1] : 0);
#pragma unroll
    for (int i = 0; i < 8; i++) s_cnt[base + i] = excl + loc[i];
    __syncthreads();

    for (int j = t; j < NUM_SPANS; j += 1024) {
        int p = atomicAdd(&s_cnt[starts[j]], 1);
        g_sorted[p] = j;
    }
}

// ---- Kernel 2: weight+value software pipeline, 4-row unroll --------------
#define FFMA8(W01, W23, W45, W67, V)            \
    do {                                        \
        ffma2(acc[0], (W01).x, (V));            \
        ffma2(acc[1], (W01).y, (V));            \
        ffma2(acc[2], (W23).x, (V));            \
        ffma2(acc[3], (W23).y, (V));            \
        ffma2(acc[4], (W45).x, (V));            \
        ffma2(acc[5], (W45).y, (V));            \
        ffma2(acc[6], (W67).x, (V));            \
        ffma2(acc[7], (W67).y, (V));            \
    } while (0)

#define LDW(dst01, dst23, dst45, dst67, ROW)                     \
    do {                                                         \
        const ulonglong2* _wr = (const ulonglong2*)s_wt[(ROW)];  \
        dst01 = _wr[0]; dst23 = _wr[1];                          \
        dst45 = _wr[2]; dst67 = _wr[3];                          \
    } while (0)

__global__ __launch_bounds__(256, 3) void span_main(
        const float* __restrict__ emb,
        const int*   __restrict__ starts,
        const int*   __restrict__ ends,
        float*       __restrict__ out) {
    __shared__ ull s_wt[WPAD][SPB];       // zero-padded weight table, 4.5 KB
    __shared__ ull s_wp[SPB][MAX_W];      // per-span weights (slow path)
    __shared__ int s_s[SPB], s_wd[SPB], s_j[SPB];

    const int tid  = threadIdx.x;         // one f32x2 column of the half-row
    const int wid  = tid >> 5;
    const int lane = tid & 31;
    const int grp  = blockIdx.x >> 1;     // span group (8 sorted spans)
    const int h    = blockIdx.x & 1;      // hidden half

    if (wid < SPB) {
        // ---- warp w: softmax for slot w ----
        int j = g_sorted[grp * SPB + wid];
        int s = starts[j];
        int W = ends[j] - s;              // width-1 in [0,31]
        float sc = (lane <= W) ? g_scores[s + lane] : -1e9f;
        float m = sc;
#pragma unroll
        for (int off = 16; off; off >>= 1)
            m = fmaxf(m, __shfl_xor_sync(0xffffffffu, m, off));
        float p = __expf(sc - m);
        float sum = p;
#pragma unroll
        for (int off = 16; off; off >>= 1)
            sum += __shfl_xor_sync(0xffffffffu, sum, off);
        float wgt = p / sum;
        s_wp[wid][lane] = packf2(wgt, wgt);
        if (lane == 0) { s_s[wid] = s; s_wd[wid] = W; s_j[wid] = j; }
    }
    // zero the padded table: WPAD*SPB = 576 ull / 256 threads
    for (int i = tid; i < WPAD * SPB; i += 256) ((ull*)s_wt)[i] = 0ull;
    __syncthreads();

    const int rmin = s_s[0];              // sorted by start
    int rmax = s_s[0] + s_wd[0];
#pragma unroll
    for (int k = 1; k < SPB; k++) rmax = max(rmax, s_s[k] + s_wd[k]);
    const int win = rmax - rmin + 1;

    const ull* colp = (const ull*)(emb) + h * HH + tid;   // + r*H2 per row
    ull*       ob   = (ull*)(out);

    if (win <= WCAP) {
        // scatter weights into the zero-padded table
        if (wid < SPB && lane <= s_wd[wid])
            s_wt[s_s[wid] - rmin + lane][wid] = s_wp[wid][lane];
        __syncthreads();

        ull acc[SPB];
#pragma unroll
        for (int k = 0; k < SPB; k++) acc[k] = 0ull;

        // ---- preload: values rows 0..3, weights rows 0..1 ----
        ull q0 = colp[(size_t)min(rmin + 0, SEQ_LEN - 1) * H2];
        ull q1 = colp[(size_t)min(rmin + 1, SEQ_LEN - 1) * H2];
        ull q2 = colp[(size_t)min(rmin + 2, SEQ_LEN - 1) * H2];
        ull q3 = colp[(size_t)min(rmin + 3, SEQ_LEN - 1) * H2];
        ulonglong2 wa01, wa23, wa45, wa67;    // weights row rw
        ulonglong2 wb01, wb23, wb45, wb67;    // weights row rw+1
        LDW(wa01, wa23, wa45, wa67, 0);
        LDW(wb01, wb23, wb45, wb67, 1);

        // ---- 4-row pipelined loop (extra rows are zero-weight no-ops) ----
        for (int rw = 0; rw < win; rw += 4) {
            // half A: rows rw, rw+1 from q0,q1 / wa,wb
            FFMA8(wa01, wa23, wa45, wa67, q0);
            FFMA8(wb01, wb23, wb45, wb67, q1);
            LDW(wa01, wa23, wa45, wa67, rw + 2);   // used in half B
            LDW(wb01, wb23, wb45, wb67, rw + 3);
            q0 = colp[(size_t)min(rmin + rw + 4, SEQ_LEN - 1) * H2];
            q1 = colp[(size_t)min(rmin + rw + 5, SEQ_LEN - 1) * H2];

            // half B: rows rw+2, rw+3 from q2,q3 / wa,wb
            FFMA8(wa01, wa23, wa45, wa67, q2);
            FFMA8(wb01, wb23, wb45, wb67, q3);
            LDW(wa01, wa23, wa45, wa67, rw + 4);   // used next iter half A
            LDW(wb01, wb23, wb45, wb67, rw + 5);
            q2 = colp[(size_t)min(rmin + rw + 6, SEQ_LEN - 1) * H2];
            q3 = colp[(size_t)min(rmin + rw + 7, SEQ_LEN - 1) * H2];
        }

        // ---- epilogue: attn_out + start/end copies ----
#pragma unroll
        for (int k = 0; k < SPB; k++) {
            int obase = s_j[k] * (3 * H2) + h * HH + tid;
            int s0 = s_s[k];
            ob[obase + 2 * H2] = acc[k];
            ob[obase]          = colp[(size_t)s0 * H2];
            ob[obase + H2]     = colp[(size_t)(s0 + s_wd[k]) * H2];
        }
    } else {
        // ---- rare slow path: sweep each span in turn ----
        for (int k = 0; k < SPB; k++) {
            int s0 = s_s[k], W = s_wd[k];
            int obase = s_j[k] * (3 * H2) + h * HH + tid;
            const ull* bp = colp + (size_t)s0 * H2;
            ull acc = 0ull;
            for (int r = 0; r <= W; r++) {
                ull w2 = s_wp[k][r];       // broadcast LDS
                ffma2(acc, w2, bp[(size_t)r * H2]);
            }
            ob[obase + 2 * H2] = acc;
            ob[obase]          = bp[0];
            ob[obase + H2]     = bp[(size_t)W * H2];
        }
    }
}

extern "C" void kernel_launch(void* const* d_in, const int* in_sizes, int n_in,
                              void* d_out, int out_size) {
    const float* emb    = (const float*)d_in[0];
    const int*   starts = (const int*)  d_in[1];
    const int*   ends   = (const int*)  d_in[2];
    const float* attn_w = (const float*)d_in[3];
    const float* attn_b = (const float*)d_in[4];
    float*       out    = (float*)d_out;

    setup_kernel<<<SCORE_BLOCKS + 1, 1024>>>(emb, attn_w, attn_b, starts);
    span_main<<<(NUM_SPANS / SPB) * 2, 256>>>(emb, starts, ends, out);
}